// round 8
// baseline (speedup 1.0000x reference)
#include <cuda_runtime.h>
#include <stdint.h>

// ---------------------------------------------------------------------------
// PGExplainer forward: masked_adj = adj * 0.5*(mask + mask^T)
// out[c,r] = cnt(c,r) * 0.5 * (S(c,r) + S(r,c)),  S = sum of sampled values
// Hash table keyed by cell id (c*N+r) holding (S, cnt); final write is an
// idempotent plain store (duplicate edges store the same value).
// ---------------------------------------------------------------------------

#define N_NODES 10000
#define N_EDGES 640000
#define D_EMB   128
#define HID     64

#define OUT_ELEMS ((size_t)N_NODES * N_NODES)   // 1e8 floats = 400 MB
#define OUT_F4    (OUT_ELEMS / 4)               // 25,000,000 float4

#define HCAP  (1 << 21)                          // hash capacity (2M slots)
#define HMASK (HCAP - 1)
#define HCAP4 (HCAP / 4)

// ---- k_prep block partition ----
#define PRE_HALF_BLOCKS 313                      // ceil(10000/32)
#define PRE_BLOCKS      (2 * PRE_HALF_BLOCKS)    // 626 (A half + B half)
#define DEC_BLOCKS      ((N_EDGES + 255) / 256)  // 2500
#define PREP_BLOCKS     (PRE_BLOCKS + DEC_BLOCKS)

// ---- k_fused block partition ----
#define EDGE_BLOCKS  2500                        // 256 edges per block
#define ZERO_BLOCKS  12500
#define ZPB4         2000                        // 12500 * 2000 = 25M exact
#define FUSED_BLOCKS (EDGE_BLOCKS + ZERO_BLOCKS)

// Scratch (device globals; hash table cleared in k_prep every call).
__device__ float g_A[N_NODES * HID];
__device__ float g_B[N_NODES * HID];
__device__ float g_noise[N_EDGES];
__device__ int2  g_ci[N_EDGES];        // decoded (col,row), clamped valid
__device__ int   g_slot[N_EDGES];      // hash slot of edge's own cell
__device__ int   g_keys[HCAP];         // -1 = empty
__device__ float g_sums[HCAP];
__device__ int   g_cnts[HCAP];

__device__ __forceinline__ uint32_t cell_hash(int key) {
    return ((uint32_t)key * 0x9E3779B1u) >> (32 - 21);   // top 21 bits
}

// ---------------------------------------------------------------------------
// threefry2x32 core (JAX rotation/key schedule), key = (0, 42)
// ---------------------------------------------------------------------------
__device__ __forceinline__ uint32_t rotl32(uint32_t x, int d) {
    return (x << d) | (x >> (32 - d));
}

__device__ __forceinline__ void threefry2x32(uint32_t k0, uint32_t k1,
                                             uint32_t x0, uint32_t x1,
                                             uint32_t& o0, uint32_t& o1) {
    uint32_t ks0 = k0, ks1 = k1, ks2 = k0 ^ k1 ^ 0x1BD11BDAu;
#define TF_R4(a, b, c, d)                            \
    x0 += x1; x1 = rotl32(x1, a); x1 ^= x0;          \
    x0 += x1; x1 = rotl32(x1, b); x1 ^= x0;          \
    x0 += x1; x1 = rotl32(x1, c); x1 ^= x0;          \
    x0 += x1; x1 = rotl32(x1, d); x1 ^= x0;
    x0 += ks0; x1 += ks1;
    TF_R4(13, 15, 26, 6);  x0 += ks1; x1 += ks2 + 1u;
    TF_R4(17, 29, 16, 24); x0 += ks2; x1 += ks0 + 2u;
    TF_R4(13, 15, 26, 6);  x0 += ks0; x1 += ks1 + 3u;
    TF_R4(17, 29, 16, 24); x0 += ks1; x1 += ks2 + 4u;
    TF_R4(13, 15, 26, 6);  x0 += ks2; x1 += ks0 + 5u;
#undef TF_R4
    o0 = x0; o1 = x1;
}

__device__ __forceinline__ float noise_from_bits(uint32_t bits) {
    float u = __uint_as_float((bits >> 9) | 0x3f800000u) - 1.0f;   // [0,1)
    return logf(u) - log1pf(-u);   // u==0 -> -inf -> sigmoid -> 0 (matches ref)
}

// ---------------------------------------------------------------------------
// K_prep: block-specialized preparation.
//   blocks [0, 626):            A/B node-level GEMM halves
//   blocks [626, 626+2500):     edge decode+clamp + threefry noise + table clear
//                               (dtype detect inlined per block, same answer
//                                everywhere: scan odd words of a fixed window)
// ---------------------------------------------------------------------------
__global__ void __launch_bounds__(256) k_prep(const float* __restrict__ embed,
                                              const float* __restrict__ W1,
                                              const void* __restrict__ ei_raw) {
    __shared__ float es[32 * D_EMB];                  // 16 KB (pre blocks only)
    __shared__ int   s_flag;

    if (blockIdx.x < PRE_BLOCKS) {
        // ---------------- per-node GEMM halves ----------------
        int half = blockIdx.x >= PRE_HALF_BLOCKS;
        int nb   = blockIdx.x - half * PRE_HALF_BLOCKS;
        int n0   = nb * 32;
        int hq   = threadIdx.x & 15;                  // h-quad: h = hq*4
        int gp   = threadIdx.x >> 4;                  // node-pair 0..15

        const float4* emb4 = (const float4*)embed;
        size_t ebase = (size_t)n0 * (D_EMB / 4);
        float4* es4 = (float4*)es;
        #pragma unroll
        for (int i = 0; i < 4; i++) {
            size_t gidx = ebase + threadIdx.x + i * 256;
            if (gidx < (size_t)N_NODES * (D_EMB / 4))
                es4[threadIdx.x + i * 256] = emb4[gidx];
        }
        __syncthreads();

        const float4* W14 = (const float4*)(W1 + (size_t)half * D_EMB * HID);
        float4 a0 = make_float4(0.f, 0.f, 0.f, 0.f);
        float4 a1 = make_float4(0.f, 0.f, 0.f, 0.f);
        const float* er0 = es + (gp * 2)     * D_EMB;
        const float* er1 = es + (gp * 2 + 1) * D_EMB;
        #pragma unroll 8
        for (int d = 0; d < D_EMB; d++) {
            float4 w  = __ldg(&W14[d * 16 + hq]);
            float  e0 = er0[d];
            float  e1 = er1[d];
            a0.x = fmaf(e0, w.x, a0.x); a0.y = fmaf(e0, w.y, a0.y);
            a0.z = fmaf(e0, w.z, a0.z); a0.w = fmaf(e0, w.w, a0.w);
            a1.x = fmaf(e1, w.x, a1.x); a1.y = fmaf(e1, w.y, a1.y);
            a1.z = fmaf(e1, w.z, a1.z); a1.w = fmaf(e1, w.w, a1.w);
        }
        float4* dst = half ? (float4*)g_B : (float4*)g_A;
        int n = n0 + gp * 2;
        if (n < N_NODES)     dst[n * 16 + hq]       = a0;
        if (n + 1 < N_NODES) dst[(n + 1) * 16 + hq] = a1;
    } else {
        // ---------------- decode + noise + table clear ----------------
        int bidx = blockIdx.x - PRE_BLOCKS;
        int e    = bidx * 256 + threadIdx.x;

        // inline dtype detect: shared fixed 32KB window -> identical result
        // in every block (int64 ids < 2^32 => odd words all zero).
        if (threadIdx.x == 0) s_flag = 0;
        __syncthreads();
        const uint32_t* ew = (const uint32_t*)ei_raw;
        int nz = 0;
        #pragma unroll
        for (int i = 0; i < 16; i++)
            nz |= (ew[2 * (threadIdx.x + i * 256) + 1] != 0u);
        if (nz) s_flag = 1;
        __syncthreads();
        int is64 = s_flag ? 0 : 1;

        // hash table clear (int4 slabs striped over decode blocks)
        if (e < HCAP4) {
            ((int4*)g_keys)[e]   = make_int4(-1, -1, -1, -1);
            ((float4*)g_sums)[e] = make_float4(0.f, 0.f, 0.f, 0.f);
            ((int4*)g_cnts)[e]   = make_int4(0, 0, 0, 0);
        }

        if (e >= N_EDGES) return;
        int c, r;
        if (is64) {
            const long long* p = (const long long*)ei_raw;
            c = (int)p[e];
            r = (int)p[N_EDGES + e];
        } else {
            const int* p = (const int*)ei_raw;
            c = p[e];
            r = p[N_EDGES + e];
        }
        c = min(max(c, 0), N_NODES - 1);
        r = min(max(r, 0), N_NODES - 1);
        g_ci[e] = make_int2(c, r);

        uint32_t o0, o1;
        threefry2x32(0u, 42u, 0u, (uint32_t)e, o0, o1);
        g_noise[e] = noise_from_bits(o0 ^ o1);
    }
}

// ---------------------------------------------------------------------------
// K_fused: block-specialized.
//   blocks [0, 2500):            edge MLP + concrete sample + hash insert
//                                (256 edges/block: 4 edges/warp x 8 iters)
//   blocks [2500, 2500+12500):   pure streaming zero of d_out (2000 float4)
// ---------------------------------------------------------------------------
__global__ void __launch_bounds__(256) k_fused(const float* __restrict__ b1,
                                               const float* __restrict__ W2,
                                               const float* __restrict__ b2,
                                               float4* __restrict__ out) {
    if (blockIdx.x >= EDGE_BLOCKS) {
        // ---------------- pure zero blocks ----------------
        const float4 z4 = make_float4(0.f, 0.f, 0.f, 0.f);
        size_t zbase = (size_t)(blockIdx.x - EDGE_BLOCKS) * ZPB4;
        #pragma unroll
        for (int i = 0; i < 7; i++)
            __stcs(&out[zbase + threadIdx.x + i * 256], z4);
        if (threadIdx.x < ZPB4 - 7 * 256)
            __stcs(&out[zbase + threadIdx.x + 7 * 256], z4);
        return;
    }

    // ---------------- edge blocks ----------------
    int warp = threadIdx.x >> 5;
    int lane = threadIdx.x & 31;
    int grp  = lane >> 3;          // edge slot within warp (0..3)
    int l8   = lane & 7;           // h-octet: handles h in [l8*8, l8*8+8)

    // invariant weights, hoisted
    const float4* b14 = (const float4*)b1;
    const float4* w24 = (const float4*)W2;
    float4 b1a = __ldg(&b14[l8 * 2]);
    float4 b1b = __ldg(&b14[l8 * 2 + 1]);
    float4 w2a = __ldg(&w24[l8 * 2]);
    float4 w2b = __ldg(&w24[l8 * 2 + 1]);
    float  bias2 = __ldg(&b2[0]);

    const float4* A4 = (const float4*)g_A;
    const float4* B4 = (const float4*)g_B;

    int ebase = blockIdx.x * 256 + warp * 4 + grp;
    #pragma unroll 2
    for (int it = 0; it < 8; it++) {
        int e = ebase + it * 32;
        int2 cr = g_ci[e];

        float4 av0 = A4[cr.x * 16 + l8 * 2];
        float4 av1 = A4[cr.x * 16 + l8 * 2 + 1];
        float4 bv0 = B4[cr.y * 16 + l8 * 2];
        float4 bv1 = B4[cr.y * 16 + l8 * 2 + 1];

        float s;
        s  = fmaxf(av0.x + bv0.x + b1a.x, 0.f) * w2a.x;
        s += fmaxf(av0.y + bv0.y + b1a.y, 0.f) * w2a.y;
        s += fmaxf(av0.z + bv0.z + b1a.z, 0.f) * w2a.z;
        s += fmaxf(av0.w + bv0.w + b1a.w, 0.f) * w2a.w;
        s += fmaxf(av1.x + bv1.x + b1b.x, 0.f) * w2b.x;
        s += fmaxf(av1.y + bv1.y + b1b.y, 0.f) * w2b.y;
        s += fmaxf(av1.z + bv1.z + b1b.z, 0.f) * w2b.z;
        s += fmaxf(av1.w + bv1.w + b1b.w, 0.f) * w2b.w;

        // reduce across the 8 lanes of this edge group
        s += __shfl_xor_sync(0xffffffffu, s, 1);
        s += __shfl_xor_sync(0xffffffffu, s, 2);
        s += __shfl_xor_sync(0xffffffffu, s, 4);

        if (l8 == 0) {
            float x = g_noise[e] + s + bias2;
            float v = 1.0f / (1.0f + expf(-x));   // sigmoid; -inf -> 0 exactly

            int key = cr.x * N_NODES + cr.y;
            uint32_t h = cell_hash(key);
            while (true) {
                int k = g_keys[h];
                if (k == key) break;
                if (k == -1) {
                    int old = atomicCAS(&g_keys[h], -1, key);
                    if (old == -1 || old == key) break;
                }
                h = (h + 1) & HMASK;
            }
            atomicAdd(&g_sums[h], v);
            atomicAdd(&g_cnts[h], 1);
            g_slot[e] = (int)h;
        }
    }
}

// ---------------------------------------------------------------------------
// K_sym: per edge, idempotent streaming store:
//   out[c,r] = cnt(c,r) * 0.5 * (S(c,r) + S(r,c))
// ---------------------------------------------------------------------------
__global__ void k_sym(float* __restrict__ out) {
    int e = blockIdx.x * blockDim.x + threadIdx.x;
    if (e >= N_EDGES) return;
    int2 cr = __ldg(&g_ci[e]);
    int slot = __ldg(&g_slot[e]);
    float S   = g_sums[slot];
    int   cnt = g_cnts[slot];

    int tkey = cr.y * N_NODES + cr.x;
    float ST = 0.0f;
    uint32_t h = cell_hash(tkey);
    while (true) {
        int k = g_keys[h];
        if (k == tkey) { ST = g_sums[h]; break; }
        if (k == -1) break;
        h = (h + 1) & HMASK;
    }
    __stcs(&out[(size_t)cr.x * N_NODES + cr.y], (float)cnt * 0.5f * (S + ST));
}

// ---------------------------------------------------------------------------
extern "C" void kernel_launch(void* const* d_in, const int* in_sizes, int n_in,
                              void* d_out, int out_size) {
    const float* embed = (const float*)d_in[0];
    const void*  ei    = d_in[1];
    const float* W1    = (const float*)d_in[2];
    const float* b1    = (const float*)d_in[3];
    const float* W2    = (const float*)d_in[4];
    const float* b2    = (const float*)d_in[5];
    float*       out   = (float*)d_out;

    // 1. prep: node GEMM halves | decode+noise+table clear (block-specialized)
    k_prep<<<PREP_BLOCKS, 256>>>(embed, W1, ei);

    // 2. fused: edge MLP/sample/hash-insert | 400 MB streaming zero
    k_fused<<<FUSED_BLOCKS, 256>>>(b1, W2, b2, (float4*)out);

    // 3. symmetrize + multiplicity -> idempotent streaming stores
    k_sym<<<(N_EDGES + 255) / 256, 256>>>(out);
}